// round 2
// baseline (speedup 1.0000x reference)
#include <cuda_runtime.h>
#include <math.h>

#define NWG   256     // waveguides
#define NP    128     // pairs per layer
#define NITER 3
#define TBR   16      // rows per CTA in build_R
#define TB    32      // batch rows per CTA in pipeline

// ---------------- scratch (no allocations allowed) ----------------
__device__ float4 g_coef[NITER * NWG * NP * 2];          // folded MZI 2x2 mats
// De-interleaved R planes (16B aligned via float4): R[k][n] = M[n][k] with gamma folded
__device__ float4 g_Rre[NITER * NWG * NWG / 4];          // Re
__device__ float4 g_Rim[NITER * NWG * NWG / 4];          // Im
__device__ float4 g_Rin[NITER * NWG * NWG / 4];          // -Im

#define HALF_G    0.07853981633974483f   // 0.5 * 0.05 * pi
#define HALF_PHIB 1.5707963267948966f    // 0.5 * pi
#define SQ09      0.9486832980505138f    // sqrt(1 - 0.1)

// ---------------- f32x2 packed helpers ----------------
__device__ __forceinline__ unsigned long long pack2(float lo, float hi) {
    unsigned long long r;
    asm("mov.b64 %0, {%1, %2};" : "=l"(r) : "f"(lo), "f"(hi));
    return r;
}
__device__ __forceinline__ void ffma2(unsigned long long& d,
                                      unsigned long long a,
                                      unsigned long long b) {
    asm("fma.rn.f32x2 %0, %1, %2, %0;" : "+l"(d) : "l"(a), "l"(b));
}
__device__ __forceinline__ float2 unpack2(unsigned long long v) {
    float2 f;
    asm("mov.b64 {%0, %1}, %2;" : "=f"(f.x), "=f"(f.y) : "l"(v));
    return f;
}

// ============================================================
// Kernel 1: fold theta/phi into 2x2 complex MZI matrices
// ============================================================
__global__ void coef_kernel(const float* __restrict__ theta,
                            const float* __restrict__ phi) {
    int t = blockIdx.x * blockDim.x + threadIdx.x;
    const int total = NITER * NWG * NP;
    if (t >= total) return;
    int pair  = t % NP;
    int layer = (t / NP) % NWG;

    float4 c01, c23;
    if ((layer & 1) && pair == NP - 1) {
        c01 = make_float4(1.f, 0.f, 0.f, 0.f);
        c23 = make_float4(0.f, 0.f, 1.f, 0.f);
    } else {
        float h = 0.5f * theta[t];
        float s, c;  sincosf(h, &s, &c);
        float sp, cp; sincosf(phi[t], &sp, &cp);
        float pre_r = -s, pre_i = c;                       // i*e^{ih}
        float pe_r = pre_r * cp - pre_i * sp;              // pre*ep
        float pe_i = pre_r * sp + pre_i * cp;
        c01 = make_float4(pe_r * s,  pe_i * s,   pre_r * c,  pre_i * c);   // A, B
        c23 = make_float4(pe_r * c,  pe_i * c,  -pre_r * s, -pre_i * s);   // C, D
    }
    g_coef[2 * t]     = c01;
    g_coef[2 * t + 1] = c23;
}

// ============================================================
// Kernel 2: build R planes via identity-basis mesh push.
// grid = (256/TBR, NITER), block = 512.
// ============================================================
__global__ void build_R_kernel(const float* __restrict__ gamma) {
    __shared__ float x0r[TBR][NP], x0i[TBR][NP], x1r[TBR][NP], x1i[TBR][NP];
    const int iter = blockIdx.y;
    const int p  = threadIdx.x & (NP - 1);
    const int rg = threadIdx.x >> 7;
    const int rbase = rg * 4;
    const int growbase = blockIdx.x * TBR;

    #pragma unroll
    for (int i = 0; i < 4; i++) {
        int r = rbase + i;
        int gj = growbase + r;
        x0r[r][p] = (2 * p     == gj) ? 1.f : 0.f;  x0i[r][p] = 0.f;
        x1r[r][p] = (2 * p + 1 == gj) ? 1.f : 0.f;  x1i[r][p] = 0.f;
    }
    __syncthreads();

    const float4* cbase = g_coef + (size_t)iter * NWG * NP * 2;
    for (int l = 0; l < NWG; l++) {
        float4 c01 = cbase[(l * NP + p) * 2];
        float4 c23 = cbase[(l * NP + p) * 2 + 1];
        float Ar = c01.x, Ai = c01.y, Br = c01.z, Bi = c01.w;
        float Cr = c23.x, Ci = c23.y, Dr = c23.z, Di = c23.w;
        bool odd = l & 1;
        if (!odd) {
            #pragma unroll
            for (int i = 0; i < 4; i++) {
                int r = rbase + i;
                float ar = x0r[r][p], ai = x0i[r][p];
                float br = x1r[r][p], bi = x1i[r][p];
                x0r[r][p] = Ar*ar - Ai*ai + Br*br - Bi*bi;
                x0i[r][p] = Ar*ai + Ai*ar + Br*bi + Bi*br;
                x1r[r][p] = Cr*ar - Ci*ai + Dr*br - Di*bi;
                x1i[r][p] = Cr*ai + Ci*ar + Dr*bi + Di*br;
            }
        } else if (p < NP - 1) {
            #pragma unroll
            for (int i = 0; i < 4; i++) {
                int r = rbase + i;
                float ar = x1r[r][p],     ai = x1i[r][p];
                float br = x0r[r][p + 1], bi = x0i[r][p + 1];
                float y0r = Ar*ar - Ai*ai + Br*br - Bi*bi;
                float y0i = Ar*ai + Ai*ar + Br*bi + Bi*br;
                float y1r = Cr*ar - Ci*ai + Dr*br - Di*bi;
                float y1i = Cr*ai + Ci*ar + Dr*bi + Di*br;
                x1r[r][p] = y0r;     x1i[r][p] = y0i;
                x0r[r][p + 1] = y1r; x0i[r][p + 1] = y1i;
            }
        }
        __syncthreads();
    }

    float s0, c0, s1, c1;
    sincosf(gamma[iter * NWG + 2 * p],     &s0, &c0);
    sincosf(gamma[iter * NWG + 2 * p + 1], &s1, &c1);
    float* Rre = (float*)g_Rre;
    float* Rim = (float*)g_Rim;
    float* Rin = (float*)g_Rin;
    #pragma unroll
    for (int i = 0; i < 4; i++) {
        int r = rbase + i;
        int gj = growbase + r;
        size_t rowoff = ((size_t)iter * NWG + gj) * NWG;
        float xr = x0r[r][p], xi = x0i[r][p];
        float rr = xr * c0 - xi * s0, ri = xr * s0 + xi * c0;
        Rre[rowoff + 2 * p] = rr;  Rim[rowoff + 2 * p] = ri;  Rin[rowoff + 2 * p] = -ri;
        xr = x1r[r][p]; xi = x1i[r][p];
        rr = xr * c1 - xi * s1;  ri = xr * s1 + xi * c1;
        Rre[rowoff + 2 * p + 1] = rr;  Rim[rowoff + 2 * p + 1] = ri;  Rin[rowoff + 2 * p + 1] = -ri;
    }
}

// ============================================================
// Kernel 3: fused batch pipeline with packed f32x2 FMAs.
// block = 256: cg = tid&63 (cols 4cg..4cg+3), rg = tid>>6 (rows 8rg..8rg+7)
// ============================================================
__global__ void __launch_bounds__(256) pipeline_kernel(
        const float* __restrict__ xre, const float* __restrict__ xim,
        float* __restrict__ out) {
    extern __shared__ float2 Xs[];        // [TB][NWG] = 64 KB
    __shared__ float red[TB];
    const int tid = threadIdx.x;
    const int rowbase = blockIdx.x * TB;

    for (int e = tid; e < TB * NWG; e += 256) {
        int r = e >> 8, n = e & (NWG - 1);
        Xs[e] = make_float2(xre[(rowbase + r) * NWG + n],
                            xim[(rowbase + r) * NWG + n]);
    }
    __syncthreads();

    const int cg = tid & 63, rg = tid >> 6;
    const int c0 = cg * 4, r0 = rg * 8;

    unsigned long long accre[8][2], accim[8][2];

    for (int it = 0; it < NITER; it++) {
        const unsigned long long zz = pack2(0.f, 0.f);
        #pragma unroll
        for (int i = 0; i < 8; i++) {
            accre[i][0] = zz; accre[i][1] = zz;
            accim[i][0] = zz; accim[i][1] = zz;
        }

        const int pbase = (it * NWG * NWG + c0) >> 2;      // float4/ulonglong2 index
        const ulonglong2* __restrict__ pr = ((const ulonglong2*)g_Rre) + pbase;
        const ulonglong2* __restrict__ pi = ((const ulonglong2*)g_Rim) + pbase;
        const ulonglong2* __restrict__ pn = ((const ulonglong2*)g_Rin) + pbase;

        #pragma unroll 2
        for (int k = 0; k < NWG; k++) {
            ulonglong2 rr = pr[k * (NWG / 4)];
            ulonglong2 ri = pi[k * (NWG / 4)];
            ulonglong2 rn = pn[k * (NWG / 4)];
            #pragma unroll
            for (int i = 0; i < 8; i++) {
                float2 xv = Xs[((r0 + i) << 8) + k];       // broadcast LDS
                unsigned long long xr2 = pack2(xv.x, xv.x);
                unsigned long long xi2 = pack2(xv.y, xv.y);
                ffma2(accre[i][0], xr2, rr.x);
                ffma2(accre[i][1], xr2, rr.y);
                ffma2(accre[i][0], xi2, rn.x);             // -= xi*Rim
                ffma2(accre[i][1], xi2, rn.y);
                ffma2(accim[i][0], xr2, ri.x);
                ffma2(accim[i][1], xr2, ri.y);
                ffma2(accim[i][0], xi2, rr.x);
                ffma2(accim[i][1], xi2, rr.y);
            }
        }
        __syncthreads();

        if (it != NITER - 1) {
            #pragma unroll
            for (int i = 0; i < 8; i++) {
                #pragma unroll
                for (int p = 0; p < 2; p++) {
                    float2 re2 = unpack2(accre[i][p]);
                    float2 im2 = unpack2(accim[i][p]);
                    float res[2][2] = {{re2.x, im2.x}, {re2.y, im2.y}};
                    #pragma unroll
                    for (int h = 0; h < 2; h++) {
                        float re = res[h][0], im = res[h][1];
                        float phase = HALF_G * (re * re + im * im) + HALF_PHIB;
                        float sp, cp; sincosf(phase, &sp, &cp);
                        float sc = SQ09 * cp;
                        Xs[((r0 + i) << 8) + c0 + 2 * p + h] =
                            make_float2(sc * (cp * re + sp * im),
                                        sc * (cp * im - sp * re));
                    }
                }
            }
            __syncthreads();
        }
    }

    // epilogue: intensity + L2-normalize(intensity) + first 10 cols
    if (tid < TB) red[tid] = 0.f;
    __syncthreads();

    float v[8][4];
    #pragma unroll
    for (int i = 0; i < 8; i++) {
        float partial = 0.f;
        #pragma unroll
        for (int p = 0; p < 2; p++) {
            float2 re2 = unpack2(accre[i][p]);
            float2 im2 = unpack2(accim[i][p]);
            v[i][2 * p]     = re2.x * re2.x + im2.x * im2.x;
            v[i][2 * p + 1] = re2.y * re2.y + im2.y * im2.y;
            partial += v[i][2 * p] * v[i][2 * p] + v[i][2 * p + 1] * v[i][2 * p + 1];
        }
        atomicAdd(&red[r0 + i], partial);
    }
    __syncthreads();

    #pragma unroll
    for (int i = 0; i < 8; i++) {
        float inv = 1.f / fmaxf(sqrtf(red[r0 + i]), 1e-12f);
        #pragma unroll
        for (int j = 0; j < 4; j++) {
            int c = c0 + j;
            if (c < 10)
                out[(rowbase + r0 + i) * 10 + c] = v[i][j] * inv;
        }
    }
}

// ============================================================
extern "C" void kernel_launch(void* const* d_in, const int* in_sizes, int n_in,
                              void* d_out, int out_size) {
    const float* xre   = (const float*)d_in[0];
    const float* xim   = (const float*)d_in[1];
    const float* theta = (const float*)d_in[2];
    const float* phi   = (const float*)d_in[3];
    const float* gamma = (const float*)d_in[4];
    float* out = (float*)d_out;

    static int smem_set = 0;
    if (!smem_set) {
        cudaFuncSetAttribute(pipeline_kernel,
                             cudaFuncAttributeMaxDynamicSharedMemorySize,
                             TB * NWG * (int)sizeof(float2));
        smem_set = 1;
    }

    coef_kernel<<<(NITER * NWG * NP + 255) / 256, 256>>>(theta, phi);
    build_R_kernel<<<dim3(NWG / TBR, NITER), 512>>>(gamma);
    pipeline_kernel<<<8192 / TB, 256, TB * NWG * sizeof(float2)>>>(xre, xim, out);
}

// round 4
// speedup vs baseline: 2.0147x; 2.0147x over previous
#include <cuda_runtime.h>
#include <cuda_bf16.h>
#include <math.h>
#include <stdint.h>

#define NWG   256
#define NP    128
#define NITER 3
#define TBR   16

#define HALF_G    0.07853981633974483f   // 0.5 * 0.05 * pi
#define HALF_PHIB 1.5707963267948966f    // 0.5 * pi
#define SQ09      0.9486832980505138f    // sqrt(1 - 0.1)

// GEMM tiling
#define BM 128
#define BN 128
#define BK 64
#define STG_PL   16384                  // bytes per smem plane (128 rows * 128B)
#define STG_BYTES (4 * STG_PL)          // Ah, Al, Bh, Bl = 64KB per stage
#define SMEM_DYN (2 * STG_BYTES)        // double buffered = 128KB
#define NKCH 8                          // 512 / 64

// ---------------- device scratch (no allocs allowed) ----------------
__device__ float4 g_coef[NITER * NWG * NP * 2];
__device__ float  g_Rre[NITER * NWG * NWG];
__device__ float  g_Rim[NITER * NWG * NWG];
__device__ __nv_bfloat16 gB_hi[NITER * 512 * 512];   // Bt[n][k] = W[k][n]
__device__ __nv_bfloat16 gB_lo[NITER * 512 * 512];
__device__ __nv_bfloat16 gA_hi[2][8192 * 512];
__device__ __nv_bfloat16 gA_lo[2][8192 * 512];
__device__ float gV[8192 * 256];

// ---------------- PTX helpers (all sm_80+ portable) ----------------
__device__ __forceinline__ void cp16(uint32_t dst, const void* src) {
    asm volatile("cp.async.cg.shared.global [%0], [%1], 16;" :: "r"(dst), "l"(src));
}
#define CP_COMMIT() asm volatile("cp.async.commit_group;" ::: "memory")
#define CP_WAIT1()  asm volatile("cp.async.wait_group 1;" ::: "memory")
#define CP_WAIT0()  asm volatile("cp.async.wait_group 0;" ::: "memory")

#define LDSM4(r, addr)                                                         \
    asm volatile("ldmatrix.sync.aligned.m8n8.x4.shared.b16 {%0,%1,%2,%3}, [%4];" \
        : "=r"((r)[0]), "=r"((r)[1]), "=r"((r)[2]), "=r"((r)[3]) : "r"(addr))

__device__ __forceinline__ void mma_bf16(float* d, const uint32_t* a,
                                         uint32_t b0, uint32_t b1) {
    asm volatile(
        "mma.sync.aligned.m16n8k16.row.col.f32.bf16.bf16.f32 "
        "{%0,%1,%2,%3}, {%4,%5,%6,%7}, {%8,%9}, {%0,%1,%2,%3};"
        : "+f"(d[0]), "+f"(d[1]), "+f"(d[2]), "+f"(d[3])
        : "r"(a[0]), "r"(a[1]), "r"(a[2]), "r"(a[3]), "r"(b0), "r"(b1));
}

// ============================================================
// Kernel 1: fold theta/phi into 2x2 complex MZI matrices
// ============================================================
__global__ void coef_kernel(const float* __restrict__ theta,
                            const float* __restrict__ phi) {
    int t = blockIdx.x * blockDim.x + threadIdx.x;
    const int total = NITER * NWG * NP;
    if (t >= total) return;
    int pair  = t % NP;
    int layer = (t / NP) % NWG;

    float4 c01, c23;
    if ((layer & 1) && pair == NP - 1) {
        c01 = make_float4(1.f, 0.f, 0.f, 0.f);
        c23 = make_float4(0.f, 0.f, 1.f, 0.f);
    } else {
        float h = 0.5f * theta[t];
        float s, c;  sincosf(h, &s, &c);
        float sp, cp; sincosf(phi[t], &sp, &cp);
        float pre_r = -s, pre_i = c;
        float pe_r = pre_r * cp - pre_i * sp;
        float pe_i = pre_r * sp + pre_i * cp;
        c01 = make_float4(pe_r * s,  pe_i * s,   pre_r * c,  pre_i * c);
        c23 = make_float4(pe_r * c,  pe_i * c,  -pre_r * s, -pre_i * s);
    }
    g_coef[2 * t]     = c01;
    g_coef[2 * t + 1] = c23;
}

// ============================================================
// Kernel 2: build R (complex transfer matrices) via identity basis
// R[a][c] = (U e_a)[c] with gamma folded.
// ============================================================
__global__ void build_R_kernel(const float* __restrict__ gamma) {
    __shared__ float x0r[TBR][NP], x0i[TBR][NP], x1r[TBR][NP], x1i[TBR][NP];
    const int iter = blockIdx.y;
    const int p  = threadIdx.x & (NP - 1);
    const int rg = threadIdx.x >> 7;
    const int rbase = rg * 4;
    const int growbase = blockIdx.x * TBR;

    #pragma unroll
    for (int i = 0; i < 4; i++) {
        int r = rbase + i;
        int gj = growbase + r;
        x0r[r][p] = (2 * p     == gj) ? 1.f : 0.f;  x0i[r][p] = 0.f;
        x1r[r][p] = (2 * p + 1 == gj) ? 1.f : 0.f;  x1i[r][p] = 0.f;
    }
    __syncthreads();

    const float4* cbase = g_coef + (size_t)iter * NWG * NP * 2;
    for (int l = 0; l < NWG; l++) {
        float4 c01 = cbase[(l * NP + p) * 2];
        float4 c23 = cbase[(l * NP + p) * 2 + 1];
        float Ar = c01.x, Ai = c01.y, Br = c01.z, Bi = c01.w;
        float Cr = c23.x, Ci = c23.y, Dr = c23.z, Di = c23.w;
        bool odd = l & 1;
        if (!odd) {
            #pragma unroll
            for (int i = 0; i < 4; i++) {
                int r = rbase + i;
                float ar = x0r[r][p], ai = x0i[r][p];
                float br = x1r[r][p], bi = x1i[r][p];
                x0r[r][p] = Ar*ar - Ai*ai + Br*br - Bi*bi;
                x0i[r][p] = Ar*ai + Ai*ar + Br*bi + Bi*br;
                x1r[r][p] = Cr*ar - Ci*ai + Dr*br - Di*bi;
                x1i[r][p] = Cr*ai + Ci*ar + Dr*bi + Di*br;
            }
        } else if (p < NP - 1) {
            #pragma unroll
            for (int i = 0; i < 4; i++) {
                int r = rbase + i;
                float ar = x1r[r][p],     ai = x1i[r][p];
                float br = x0r[r][p + 1], bi = x0i[r][p + 1];
                float y0r = Ar*ar - Ai*ai + Br*br - Bi*bi;
                float y0i = Ar*ai + Ai*ar + Br*bi + Bi*br;
                float y1r = Cr*ar - Ci*ai + Dr*br - Di*bi;
                float y1i = Cr*ai + Ci*ar + Dr*bi + Di*br;
                x1r[r][p] = y0r;     x1i[r][p] = y0i;
                x0r[r][p + 1] = y1r; x0i[r][p + 1] = y1i;
            }
        }
        __syncthreads();
    }

    float s0, c0, s1, c1;
    sincosf(gamma[iter * NWG + 2 * p],     &s0, &c0);
    sincosf(gamma[iter * NWG + 2 * p + 1], &s1, &c1);
    #pragma unroll
    for (int i = 0; i < 4; i++) {
        int r = rbase + i;
        int gj = growbase + r;
        size_t rowoff = ((size_t)iter * NWG + gj) * NWG;
        float xr = x0r[r][p], xi = x0i[r][p];
        g_Rre[rowoff + 2 * p] = xr * c0 - xi * s0;
        g_Rim[rowoff + 2 * p] = xr * s0 + xi * c0;
        xr = x1r[r][p]; xi = x1i[r][p];
        g_Rre[rowoff + 2 * p + 1] = xr * c1 - xi * s1;
        g_Rim[rowoff + 2 * p + 1] = xr * s1 + xi * c1;
    }
}

// ============================================================
// Kernel 3: pack W^T into bf16 hi/lo planes.
// W[2a][2c]=Rr, W[2a+1][2c]=-Ri, W[2a][2c+1]=Ri, W[2a+1][2c+1]=Rr
// gB[it][n][k] = W[k][n]
// ============================================================
__global__ void pack_W_kernel() {
    int t = blockIdx.x * blockDim.x + threadIdx.x;
    if (t >= NITER * 512 * 512) return;
    int k = t & 511;
    int n = (t >> 9) & 511;
    int it = t >> 18;
    int a = k >> 1, c = n >> 1;
    int kb = k & 1, nb = n & 1;
    size_t ri = ((size_t)it * NWG + a) * NWG + c;
    float val;
    if (kb == nb)      val = g_Rre[ri];
    else if (kb == 1)  val = -g_Rim[ri];
    else               val = g_Rim[ri];
    __nv_bfloat16 h = __float2bfloat16_rn(val);
    gB_hi[t] = h;
    gB_lo[t] = __float2bfloat16_rn(val - __bfloat162float(h));
}

// ============================================================
// Kernel 4: prep A0 (interleaved re/im, bf16 hi/lo)
// ============================================================
__global__ void prep_A_kernel(const float* __restrict__ xr,
                              const float* __restrict__ xi) {
    int t = blockIdx.x * blockDim.x + threadIdx.x;
    if (t >= 8192 * 256) return;
    int c = t & 255, m = t >> 8;
    size_t o = (size_t)m * 512 + 2 * c;
    float vr = xr[t], vi = xi[t];
    __nv_bfloat16 h = __float2bfloat16_rn(vr);
    gA_hi[0][o] = h;
    gA_lo[0][o] = __float2bfloat16_rn(vr - __bfloat162float(h));
    h = __float2bfloat16_rn(vi);
    gA_hi[0][o + 1] = h;
    gA_lo[0][o + 1] = __float2bfloat16_rn(vi - __bfloat162float(h));
}

// ============================================================
// Kernel 5: bf16 split-2 GEMM via mma.sync + fused epilogue.
// Y[m][n] = sum_k A[m][k] * W[k][n] (bf16: ah*bh + ah*bl + al*bh)
// grid (64, 4), 256 threads = 8 warps; warp tile 64x32.
// ============================================================
__global__ void __launch_bounds__(256, 1) gemm_kernel(int iter) {
    extern __shared__ char smraw[];
    const uint32_t smem_u = (uint32_t)__cvta_generic_to_shared(smraw);

    const int tid = threadIdx.x;
    const int lane = tid & 31, wid = tid >> 5;
    const int wm = wid & 1, wn = wid >> 1;
    const int m0 = blockIdx.x * BM;
    const int n0 = blockIdx.y * BN;
    const int rd = iter & 1;

    const __nv_bfloat16* __restrict__ Ah = gA_hi[rd];
    const __nv_bfloat16* __restrict__ Al = gA_lo[rd];
    const __nv_bfloat16* __restrict__ Bh = gB_hi + (size_t)iter * 512 * 512;
    const __nv_bfloat16* __restrict__ Bl = gB_lo + (size_t)iter * 512 * 512;
    const __nv_bfloat16* planes[4] = { Ah, Al, Bh, Bl };

    // --- async loader for one K-chunk into stage buf ---
    auto issue_loads = [&](int ch, int buf) {
        const int k0 = ch * BK;
        uint32_t sbase = smem_u + buf * STG_BYTES;
        #pragma unroll
        for (int pl = 0; pl < 4; pl++) {
            const __nv_bfloat16* src = planes[pl];
            int rowbase = (pl < 2) ? m0 : n0;
            #pragma unroll
            for (int qq = 0; qq < 4; qq++) {
                int q = qq * 256 + tid;
                int row = q >> 3, c = q & 7;
                const void* g = src + (size_t)(rowbase + row) * 512 + k0 + c * 8;
                uint32_t d = sbase + pl * STG_PL + row * 128 + ((c ^ (row & 7)) << 4);
                cp16(d, g);
            }
        }
    };

    // ldmatrix row/swizzle precompute
    int rowA[4], rowB[2];
    #pragma unroll
    for (int ms = 0; ms < 4; ms++)
        rowA[ms] = wm * 64 + ms * 16 + ((lane >> 3) & 1) * 8 + (lane & 7);
    #pragma unroll
    for (int nb = 0; nb < 2; nb++)
        rowB[nb] = wn * 32 + nb * 16 + ((lane >> 3) & 1) * 8 + (lane & 7);
    const int khalf = lane >> 4;   // 0/1

    float acc[4][4][4];
    #pragma unroll
    for (int i = 0; i < 4; i++)
        #pragma unroll
        for (int j = 0; j < 4; j++)
            #pragma unroll
            for (int q = 0; q < 4; q++) acc[i][j][q] = 0.f;

    issue_loads(0, 0);
    CP_COMMIT();

    for (int ch = 0; ch < NKCH; ch++) {
        const int b = ch & 1;
        if (ch + 1 < NKCH) {
            issue_loads(ch + 1, (ch + 1) & 1);
            CP_COMMIT();
            CP_WAIT1();
        } else {
            CP_WAIT0();
        }
        __syncthreads();

        const uint32_t stbase = smem_u + b * STG_BYTES;
        #pragma unroll
        for (int kk = 0; kk < 4; kk++) {
            const int kidx = kk * 2 + khalf;
            uint32_t ah[4][4], al[4][4], bh[2][4], bl[2][4];
            #pragma unroll
            for (int ms = 0; ms < 4; ms++) {
                uint32_t ad = stbase + rowA[ms] * 128 + ((kidx ^ (rowA[ms] & 7)) << 4);
                LDSM4(ah[ms], ad);
                LDSM4(al[ms], ad + STG_PL);
            }
            #pragma unroll
            for (int nb = 0; nb < 2; nb++) {
                uint32_t bd = stbase + 2 * STG_PL + rowB[nb] * 128
                            + ((kidx ^ (rowB[nb] & 7)) << 4);
                LDSM4(bh[nb], bd);
                LDSM4(bl[nb], bd + STG_PL);
            }
            #pragma unroll
            for (int ms = 0; ms < 4; ms++) {
                #pragma unroll
                for (int ns = 0; ns < 4; ns++) {
                    int nb = ns >> 1, od = ns & 1;
                    mma_bf16(acc[ms][ns], ah[ms], bh[nb][od], bh[nb][2 + od]);
                    mma_bf16(acc[ms][ns], ah[ms], bl[nb][od], bl[nb][2 + od]);
                    mma_bf16(acc[ms][ns], al[ms], bh[nb][od], bh[nb][2 + od]);
                }
            }
        }
        __syncthreads();
    }

    // --- fused epilogue (fragment (re,im) pairs are thread-local) ---
    const int nxt = (iter + 1) & 1;
    const int rowbase = m0 + wm * 64 + (lane >> 2);
    const int colbase = n0 + wn * 32 + (lane & 3) * 2;

    #pragma unroll
    for (int ms = 0; ms < 4; ms++) {
        #pragma unroll
        for (int ns = 0; ns < 4; ns++) {
            #pragma unroll
            for (int h = 0; h < 2; h++) {
                int row = rowbase + ms * 16 + h * 8;
                int col = colbase + ns * 8;
                float re = acc[ms][ns][2 * h];
                float im = acc[ms][ns][2 * h + 1];
                if (iter != NITER - 1) {
                    float phase = HALF_G * (re * re + im * im) + HALF_PHIB;
                    float sp, cp; sincosf(phase, &sp, &cp);
                    float sc = SQ09 * cp;
                    float yre = sc * (cp * re + sp * im);
                    float yim = sc * (cp * im - sp * re);
                    __nv_bfloat16 hr = __float2bfloat16_rn(yre);
                    __nv_bfloat16 hi = __float2bfloat16_rn(yim);
                    __nv_bfloat16 lr = __float2bfloat16_rn(yre - __bfloat162float(hr));
                    __nv_bfloat16 li = __float2bfloat16_rn(yim - __bfloat162float(hi));
                    size_t o = (size_t)row * 512 + col;
                    *(__nv_bfloat162*)(gA_hi[nxt] + o) = __nv_bfloat162(hr, hi);
                    *(__nv_bfloat162*)(gA_lo[nxt] + o) = __nv_bfloat162(lr, li);
                } else {
                    gV[(size_t)row * 256 + (col >> 1)] = re * re + im * im;
                }
            }
        }
    }
}

// ============================================================
// Kernel 6: row-wise L2 normalize of intensity, write 10 cols
// ============================================================
__global__ void normalize_kernel(float* __restrict__ out) {
    int w = (blockIdx.x * blockDim.x + threadIdx.x) >> 5;
    int lane = threadIdx.x & 31;
    if (w >= 8192) return;
    const float* v = gV + (size_t)w * 256;
    float first = 0.f, sum = 0.f;
    #pragma unroll
    for (int j = 0; j < 8; j++) {
        float x = v[lane + 32 * j];
        if (j == 0) first = x;
        sum += x * x;
    }
    #pragma unroll
    for (int o = 16; o; o >>= 1) sum += __shfl_xor_sync(0xFFFFFFFFu, sum, o);
    float inv = 1.f / fmaxf(sqrtf(sum), 1e-12f);
    if (lane < 10) out[w * 10 + lane] = first * inv;
}

// ============================================================
extern "C" void kernel_launch(void* const* d_in, const int* in_sizes, int n_in,
                              void* d_out, int out_size) {
    const float* xre   = (const float*)d_in[0];
    const float* xim   = (const float*)d_in[1];
    const float* theta = (const float*)d_in[2];
    const float* phi   = (const float*)d_in[3];
    const float* gamma = (const float*)d_in[4];
    float* out = (float*)d_out;

    static int attr_set = 0;
    if (!attr_set) {
        cudaFuncSetAttribute(gemm_kernel,
                             cudaFuncAttributeMaxDynamicSharedMemorySize, SMEM_DYN);
        attr_set = 1;
    }

    coef_kernel<<<(NITER * NWG * NP + 255) / 256, 256>>>(theta, phi);
    build_R_kernel<<<dim3(NWG / TBR, NITER), 512>>>(gamma);
    pack_W_kernel<<<(NITER * 512 * 512) / 256, 256>>>();
    prep_A_kernel<<<(8192 * 256) / 256, 256>>>(xre, xim);
    for (int it = 0; it < NITER; it++)
        gemm_kernel<<<dim3(8192 / BM, 512 / BN), 256, SMEM_DYN>>>(it);
    normalize_kernel<<<8192 / 8, 256>>>(out);
}

// round 5
// speedup vs baseline: 2.3936x; 1.1880x over previous
#include <cuda_runtime.h>
#include <cuda_bf16.h>
#include <math.h>
#include <stdint.h>

#define NWG   256
#define NP    128
#define NITER 3
#define TBR   4

#define HALF_G    0.07853981633974483f   // 0.5 * 0.05 * pi
#define HALF_PHIB 1.5707963267948966f    // 0.5 * pi
#define SQ09      0.9486832980505138f    // sqrt(1 - 0.1)

// GEMM tiling
#define BM 128
#define BN 128
#define BK 32
#define NKCH 16                          // 512 / 32
#define STG_PL   8192                    // bytes per plane per stage (128 rows * 64B)
#define STG_BYTES (4 * STG_PL)           // Ah, Al, Bh, Bl = 32KB per stage
#define NSTG 3
#define SMEM_DYN (NSTG * STG_BYTES)      // 96KB

// ---------------- device scratch (no allocs allowed) ----------------
__device__ float4 g_coef[NITER * NWG * NP * 2];
__device__ float  g_Rre[NITER * NWG * NWG];
__device__ float  g_Rim[NITER * NWG * NWG];
__device__ __nv_bfloat16 gB_hi[NITER * 512 * 512];   // Bt[n][k] = W[k][n]
__device__ __nv_bfloat16 gB_lo[NITER * 512 * 512];
__device__ __nv_bfloat16 gA_hi[2][8192 * 512];
__device__ __nv_bfloat16 gA_lo[2][8192 * 512];
__device__ float gV[8192 * 256];

// ---------------- PTX helpers (sm_80+ portable) ----------------
__device__ __forceinline__ void cp16(uint32_t dst, const void* src) {
    asm volatile("cp.async.cg.shared.global [%0], [%1], 16;" :: "r"(dst), "l"(src));
}
#define CP_COMMIT() asm volatile("cp.async.commit_group;" ::: "memory")
#define CP_WAIT2()  asm volatile("cp.async.wait_group 2;" ::: "memory")
#define CP_WAIT1()  asm volatile("cp.async.wait_group 1;" ::: "memory")
#define CP_WAIT0()  asm volatile("cp.async.wait_group 0;" ::: "memory")

#define LDSM4(r, addr)                                                         \
    asm volatile("ldmatrix.sync.aligned.m8n8.x4.shared.b16 {%0,%1,%2,%3}, [%4];" \
        : "=r"((r)[0]), "=r"((r)[1]), "=r"((r)[2]), "=r"((r)[3]) : "r"(addr))

__device__ __forceinline__ void mma_bf16(float* d, const uint32_t* a,
                                         uint32_t b0, uint32_t b1) {
    asm volatile(
        "mma.sync.aligned.m16n8k16.row.col.f32.bf16.bf16.f32 "
        "{%0,%1,%2,%3}, {%4,%5,%6,%7}, {%8,%9}, {%0,%1,%2,%3};"
        : "+f"(d[0]), "+f"(d[1]), "+f"(d[2]), "+f"(d[3])
        : "r"(a[0]), "r"(a[1]), "r"(a[2]), "r"(a[3]), "r"(b0), "r"(b1));
}

// smem swizzle: 64B rows, 4 x 16B chunks; conflict-free for ldmatrix
__device__ __forceinline__ uint32_t swz(int row, int c) {
    return (uint32_t)(row * 64 + ((c ^ ((row >> 1) & 3)) << 4));
}

// ============================================================
// Kernel 1: fold theta/phi into 2x2 complex MZI matrices
// ============================================================
__global__ void coef_kernel(const float* __restrict__ theta,
                            const float* __restrict__ phi) {
    int t = blockIdx.x * blockDim.x + threadIdx.x;
    const int total = NITER * NWG * NP;
    if (t >= total) return;
    int pair  = t % NP;
    int layer = (t / NP) % NWG;

    float4 c01, c23;
    if ((layer & 1) && pair == NP - 1) {
        c01 = make_float4(1.f, 0.f, 0.f, 0.f);
        c23 = make_float4(0.f, 0.f, 1.f, 0.f);
    } else {
        float h = 0.5f * theta[t];
        float s, c;  sincosf(h, &s, &c);
        float sp, cp; sincosf(phi[t], &sp, &cp);
        float pre_r = -s, pre_i = c;
        float pe_r = pre_r * cp - pre_i * sp;
        float pe_i = pre_r * sp + pre_i * cp;
        c01 = make_float4(pe_r * s,  pe_i * s,   pre_r * c,  pre_i * c);
        c23 = make_float4(pe_r * c,  pe_i * c,  -pre_r * s, -pre_i * s);
    }
    g_coef[2 * t]     = c01;
    g_coef[2 * t + 1] = c23;
}

// ============================================================
// Kernel 2: build R via identity basis. grid (64, 3), block 512.
// 1 basis row per 128-thread group (TBR=4 rows per CTA).
// ============================================================
__global__ void build_R_kernel(const float* __restrict__ gamma) {
    __shared__ float x0r[TBR][NP], x0i[TBR][NP], x1r[TBR][NP], x1i[TBR][NP];
    const int iter = blockIdx.y;
    const int p = threadIdx.x & (NP - 1);
    const int r = threadIdx.x >> 7;            // 0..3
    const int gj = blockIdx.x * TBR + r;       // global basis index

    x0r[r][p] = (2 * p     == gj) ? 1.f : 0.f;  x0i[r][p] = 0.f;
    x1r[r][p] = (2 * p + 1 == gj) ? 1.f : 0.f;  x1i[r][p] = 0.f;
    __syncthreads();

    const float4* cbase = g_coef + (size_t)iter * NWG * NP * 2;
    for (int l = 0; l < NWG; l++) {
        float4 c01 = cbase[(l * NP + p) * 2];
        float4 c23 = cbase[(l * NP + p) * 2 + 1];
        float Ar = c01.x, Ai = c01.y, Br = c01.z, Bi = c01.w;
        float Cr = c23.x, Ci = c23.y, Dr = c23.z, Di = c23.w;
        if (!(l & 1)) {
            float ar = x0r[r][p], ai = x0i[r][p];
            float br = x1r[r][p], bi = x1i[r][p];
            x0r[r][p] = Ar*ar - Ai*ai + Br*br - Bi*bi;
            x0i[r][p] = Ar*ai + Ai*ar + Br*bi + Bi*br;
            x1r[r][p] = Cr*ar - Ci*ai + Dr*br - Di*bi;
            x1i[r][p] = Cr*ai + Ci*ar + Dr*bi + Di*br;
        } else if (p < NP - 1) {
            float ar = x1r[r][p],     ai = x1i[r][p];
            float br = x0r[r][p + 1], bi = x0i[r][p + 1];
            float y0r = Ar*ar - Ai*ai + Br*br - Bi*bi;
            float y0i = Ar*ai + Ai*ar + Br*bi + Bi*br;
            float y1r = Cr*ar - Ci*ai + Dr*br - Di*bi;
            float y1i = Cr*ai + Ci*ar + Dr*bi + Di*br;
            x1r[r][p] = y0r;     x1i[r][p] = y0i;
            x0r[r][p + 1] = y1r; x0i[r][p + 1] = y1i;
        }
        __syncthreads();
    }

    float s0, c0, s1, c1;
    sincosf(gamma[iter * NWG + 2 * p],     &s0, &c0);
    sincosf(gamma[iter * NWG + 2 * p + 1], &s1, &c1);
    size_t rowoff = ((size_t)iter * NWG + gj) * NWG;
    float xr = x0r[r][p], xi = x0i[r][p];
    g_Rre[rowoff + 2 * p] = xr * c0 - xi * s0;
    g_Rim[rowoff + 2 * p] = xr * s0 + xi * c0;
    xr = x1r[r][p]; xi = x1i[r][p];
    g_Rre[rowoff + 2 * p + 1] = xr * c1 - xi * s1;
    g_Rim[rowoff + 2 * p + 1] = xr * s1 + xi * c1;
}

// ============================================================
// Kernel 3: pack W^T into bf16 hi/lo planes.
// ============================================================
__global__ void pack_W_kernel() {
    int t = blockIdx.x * blockDim.x + threadIdx.x;
    if (t >= NITER * 512 * 512) return;
    int k = t & 511;
    int n = (t >> 9) & 511;
    int it = t >> 18;
    int a = k >> 1, c = n >> 1;
    int kb = k & 1, nb = n & 1;
    size_t ri = ((size_t)it * NWG + a) * NWG + c;
    float val;
    if (kb == nb)      val = g_Rre[ri];
    else if (kb == 1)  val = -g_Rim[ri];
    else               val = g_Rim[ri];
    __nv_bfloat16 h = __float2bfloat16_rn(val);
    gB_hi[t] = h;
    gB_lo[t] = __float2bfloat16_rn(val - __bfloat162float(h));
}

// ============================================================
// Kernel 4: prep A0 (vectorized: float4 in, uint4 out)
// ============================================================
__global__ void prep_A_kernel(const float* __restrict__ xr,
                              const float* __restrict__ xi) {
    int t = blockIdx.x * blockDim.x + threadIdx.x;
    if (t >= 8192 * 64) return;
    int cq = t & 63, m = t >> 6;
    float4 vr = *(const float4*)(xr + (size_t)m * 256 + cq * 4);
    float4 vi = *(const float4*)(xi + (size_t)m * 256 + cq * 4);
    float re[4] = { vr.x, vr.y, vr.z, vr.w };
    float im[4] = { vi.x, vi.y, vi.z, vi.w };
    __align__(16) __nv_bfloat16 hb[8], lb[8];
    #pragma unroll
    for (int q = 0; q < 4; q++) {
        __nv_bfloat16 h = __float2bfloat16_rn(re[q]);
        hb[2 * q] = h;  lb[2 * q] = __float2bfloat16_rn(re[q] - __bfloat162float(h));
        h = __float2bfloat16_rn(im[q]);
        hb[2 * q + 1] = h;  lb[2 * q + 1] = __float2bfloat16_rn(im[q] - __bfloat162float(h));
    }
    size_t o = (size_t)m * 512 + cq * 8;
    *(uint4*)(gA_hi[0] + o) = *(const uint4*)hb;
    *(uint4*)(gA_lo[0] + o) = *(const uint4*)lb;
}

// ============================================================
// Kernel 5: bf16 split-2 GEMM (mma.sync) + fused epilogue.
// grid (64, 4), 256 threads = 8 warps; warp tile 64x32; 2 CTAs/SM.
// ============================================================
__global__ void __launch_bounds__(256, 2) gemm_kernel(int iter) {
    extern __shared__ char smraw[];
    const uint32_t smem_u = (uint32_t)__cvta_generic_to_shared(smraw);

    const int tid = threadIdx.x;
    const int lane = tid & 31, wid = tid >> 5;
    const int wm = wid & 1, wn = wid >> 1;
    const int m0 = blockIdx.x * BM;
    const int n0 = blockIdx.y * BN;
    const int rd = iter & 1;

    const __nv_bfloat16* __restrict__ Ah = gA_hi[rd];
    const __nv_bfloat16* __restrict__ Al = gA_lo[rd];
    const __nv_bfloat16* __restrict__ Bh = gB_hi + (size_t)iter * 512 * 512;
    const __nv_bfloat16* __restrict__ Bl = gB_lo + (size_t)iter * 512 * 512;
    const __nv_bfloat16* planes[4] = { Ah, Al, Bh, Bl };

    // loader: one K-chunk (BK=32) into stage buf. 2048 cp16 = 8/thread.
    auto issue_loads = [&](int ch, int buf) {
        const int k0 = ch * BK;
        uint32_t sbase = smem_u + buf * STG_BYTES;
        #pragma unroll
        for (int pl = 0; pl < 4; pl++) {
            const __nv_bfloat16* src = planes[pl];
            int rowbase = (pl < 2) ? m0 : n0;
            #pragma unroll
            for (int qq = 0; qq < 2; qq++) {
                int q = qq * 256 + tid;
                int row = q >> 2, c = q & 3;
                const void* g = src + (size_t)(rowbase + row) * 512 + k0 + c * 8;
                cp16(sbase + pl * STG_PL + swz(row, c), g);
            }
        }
    };

    int rowA[4], rowB[2];
    #pragma unroll
    for (int ms = 0; ms < 4; ms++)
        rowA[ms] = wm * 64 + ms * 16 + ((lane >> 3) & 1) * 8 + (lane & 7);
    #pragma unroll
    for (int nb = 0; nb < 2; nb++)
        rowB[nb] = wn * 32 + nb * 16 + ((lane >> 3) & 1) * 8 + (lane & 7);
    const int khalf = lane >> 4;   // 0/1

    float acc[4][4][4];
    #pragma unroll
    for (int i = 0; i < 4; i++)
        #pragma unroll
        for (int j = 0; j < 4; j++)
            #pragma unroll
            for (int q = 0; q < 4; q++) acc[i][j][q] = 0.f;

    issue_loads(0, 0); CP_COMMIT();
    issue_loads(1, 1); CP_COMMIT();

    for (int ch = 0; ch < NKCH; ch++) {
        const int b = ch % NSTG;
        if (ch + 2 < NKCH) {
            issue_loads(ch + 2, (ch + 2) % NSTG);
            CP_COMMIT();
            CP_WAIT2();
        } else if (ch + 1 < NKCH) {
            CP_WAIT1();
        } else {
            CP_WAIT0();
        }
        __syncthreads();

        const uint32_t stbase = smem_u + b * STG_BYTES;
        #pragma unroll
        for (int kk = 0; kk < 2; kk++) {
            const int kidx = kk * 2 + khalf;
            uint32_t bh[2][4], bl[2][4];
            #pragma unroll
            for (int nb = 0; nb < 2; nb++) {
                uint32_t bd = stbase + 2 * STG_PL + swz(rowB[nb], kidx);
                LDSM4(bh[nb], bd);
                LDSM4(bl[nb], bd + STG_PL);
            }
            #pragma unroll
            for (int ms = 0; ms < 4; ms++) {
                uint32_t ah[4], al[4];
                uint32_t ad = stbase + swz(rowA[ms], kidx);
                LDSM4(ah, ad);
                LDSM4(al, ad + STG_PL);
                #pragma unroll
                for (int ns = 0; ns < 4; ns++) {
                    int nb = ns >> 1, od = ns & 1;
                    mma_bf16(acc[ms][ns], ah, bh[nb][od], bh[nb][2 + od]);
                    mma_bf16(acc[ms][ns], ah, bl[nb][od], bl[nb][2 + od]);
                    mma_bf16(acc[ms][ns], al, bh[nb][od], bh[nb][2 + od]);
                }
            }
        }
        __syncthreads();
    }

    // fused epilogue (fragment (re,im) pairs are thread-local)
    const int nxt = (iter + 1) & 1;
    const int rowbase = m0 + wm * 64 + (lane >> 2);
    const int colbase = n0 + wn * 32 + (lane & 3) * 2;

    #pragma unroll
    for (int ms = 0; ms < 4; ms++) {
        #pragma unroll
        for (int ns = 0; ns < 4; ns++) {
            #pragma unroll
            for (int h = 0; h < 2; h++) {
                int row = rowbase + ms * 16 + h * 8;
                int col = colbase + ns * 8;
                float re = acc[ms][ns][2 * h];
                float im = acc[ms][ns][2 * h + 1];
                if (iter != NITER - 1) {
                    float phase = HALF_G * (re * re + im * im) + HALF_PHIB;
                    float sp, cp; sincosf(phase, &sp, &cp);
                    float sc = SQ09 * cp;
                    float yre = sc * (cp * re + sp * im);
                    float yim = sc * (cp * im - sp * re);
                    __nv_bfloat16 hr = __float2bfloat16_rn(yre);
                    __nv_bfloat16 hi = __float2bfloat16_rn(yim);
                    __nv_bfloat16 lr = __float2bfloat16_rn(yre - __bfloat162float(hr));
                    __nv_bfloat16 li = __float2bfloat16_rn(yim - __bfloat162float(hi));
                    size_t o = (size_t)row * 512 + col;
                    *(__nv_bfloat162*)(gA_hi[nxt] + o) = __nv_bfloat162(hr, hi);
                    *(__nv_bfloat162*)(gA_lo[nxt] + o) = __nv_bfloat162(lr, li);
                } else {
                    gV[(size_t)row * 256 + (col >> 1)] = re * re + im * im;
                }
            }
        }
    }
}

// ============================================================
// Kernel 6: row-wise L2 normalize of intensity, write 10 cols
// ============================================================
__global__ void normalize_kernel(float* __restrict__ out) {
    int w = (blockIdx.x * blockDim.x + threadIdx.x) >> 5;
    int lane = threadIdx.x & 31;
    if (w >= 8192) return;
    const float* v = gV + (size_t)w * 256;
    float first = 0.f, sum = 0.f;
    #pragma unroll
    for (int j = 0; j < 8; j++) {
        float x = v[lane + 32 * j];
        if (j == 0) first = x;
        sum += x * x;
    }
    #pragma unroll
    for (int o = 16; o; o >>= 1) sum += __shfl_xor_sync(0xFFFFFFFFu, sum, o);
    float inv = 1.f / fmaxf(sqrtf(sum), 1e-12f);
    if (lane < 10) out[w * 10 + lane] = first * inv;
}

// ============================================================
extern "C" void kernel_launch(void* const* d_in, const int* in_sizes, int n_in,
                              void* d_out, int out_size) {
    const float* xre   = (const float*)d_in[0];
    const float* xim   = (const float*)d_in[1];
    const float* theta = (const float*)d_in[2];
    const float* phi   = (const float*)d_in[3];
    const float* gamma = (const float*)d_in[4];
    float* out = (float*)d_out;

    static int attr_set = 0;
    if (!attr_set) {
        cudaFuncSetAttribute(gemm_kernel,
                             cudaFuncAttributeMaxDynamicSharedMemorySize, SMEM_DYN);
        attr_set = 1;
    }

    coef_kernel<<<(NITER * NWG * NP + 255) / 256, 256>>>(theta, phi);
    build_R_kernel<<<dim3(NWG / TBR, NITER), 512>>>(gamma);
    pack_W_kernel<<<(NITER * 512 * 512) / 256, 256>>>();
    prep_A_kernel<<<(8192 * 64) / 256, 256>>>(xre, xim);
    for (int it = 0; it < NITER; it++)
        gemm_kernel<<<dim3(8192 / BM, 512 / BN), 256, SMEM_DYN>>>(it);
    normalize_kernel<<<8192 / 8, 256>>>(out);
}

// round 6
// speedup vs baseline: 2.4267x; 1.0138x over previous
#include <cuda_runtime.h>
#include <cuda_bf16.h>
#include <math.h>
#include <stdint.h>

#define NWG   256
#define NP    128
#define NITER 3
#define TBR   4

#define HALF_G    0.07853981633974483f   // 0.5 * 0.05 * pi
#define HALF_PHIB 1.5707963267948966f    // 0.5 * pi
#define SQ09      0.9486832980505138f    // sqrt(1 - 0.1)

// GEMM tiling
#define BM 128
#define BN 128
#define BK 32
#define NKCH 16                          // 512 / 32
#define STG_PL   8192                    // bytes per plane per stage (128 rows * 64B)
#define STG_BYTES (4 * STG_PL)           // Ah, Al, Bh, Bl = 32KB per stage
#define NSTG 3
#define SMEM_DYN (NSTG * STG_BYTES)      // 96KB

// ---------------- device scratch (no allocs allowed) ----------------
__device__ float4 g_coef[NITER * NWG * NP * 2];
__device__ float  g_Rre[NITER * NWG * NWG];
__device__ float  g_Rim[NITER * NWG * NWG];
__device__ __nv_bfloat16 gB_hi[NITER * 512 * 512];   // Bt[n][k] = W[k][n]
__device__ __nv_bfloat16 gB_lo[NITER * 512 * 512];
__device__ __nv_bfloat16 gA_hi[2][8192 * 512];
__device__ __nv_bfloat16 gA_lo[2][8192 * 512];
__device__ float gV[8192 * 256];

// ---------------- PTX helpers (sm_80+ portable) ----------------
__device__ __forceinline__ void cp16(uint32_t dst, const void* src) {
    asm volatile("cp.async.cg.shared.global [%0], [%1], 16;" :: "r"(dst), "l"(src));
}
#define CP_COMMIT() asm volatile("cp.async.commit_group;" ::: "memory")
#define CP_WAIT1()  asm volatile("cp.async.wait_group 1;" ::: "memory")
#define CP_WAIT0()  asm volatile("cp.async.wait_group 0;" ::: "memory")

#define LDSM4(r, addr)                                                         \
    asm volatile("ldmatrix.sync.aligned.m8n8.x4.shared.b16 {%0,%1,%2,%3}, [%4];" \
        : "=r"((r)[0]), "=r"((r)[1]), "=r"((r)[2]), "=r"((r)[3]) : "r"(addr))

__device__ __forceinline__ void mma_bf16(float* d, const uint32_t* a,
                                         uint32_t b0, uint32_t b1) {
    asm volatile(
        "mma.sync.aligned.m16n8k16.row.col.f32.bf16.bf16.f32 "
        "{%0,%1,%2,%3}, {%4,%5,%6,%7}, {%8,%9}, {%0,%1,%2,%3};"
        : "+f"(d[0]), "+f"(d[1]), "+f"(d[2]), "+f"(d[3])
        : "r"(a[0]), "r"(a[1]), "r"(a[2]), "r"(a[3]), "r"(b0), "r"(b1));
}

// smem swizzle: 64B rows, 4 x 16B chunks; conflict-free for ldmatrix + stores
__device__ __forceinline__ uint32_t swz(int row, int c) {
    return (uint32_t)(row * 64 + ((c ^ ((row >> 1) & 3)) << 4));
}

// ============================================================
// Kernel 1: fold theta/phi into 2x2 complex MZI matrices
// ============================================================
__global__ void coef_kernel(const float* __restrict__ theta,
                            const float* __restrict__ phi) {
    int t = blockIdx.x * blockDim.x + threadIdx.x;
    const int total = NITER * NWG * NP;
    if (t >= total) return;
    int pair  = t % NP;
    int layer = (t / NP) % NWG;

    float4 c01, c23;
    if ((layer & 1) && pair == NP - 1) {
        c01 = make_float4(1.f, 0.f, 0.f, 0.f);
        c23 = make_float4(0.f, 0.f, 1.f, 0.f);
    } else {
        float h = 0.5f * theta[t];
        float s, c;  sincosf(h, &s, &c);
        float sp, cp; sincosf(phi[t], &sp, &cp);
        float pre_r = -s, pre_i = c;
        float pe_r = pre_r * cp - pre_i * sp;
        float pe_i = pre_r * sp + pre_i * cp;
        c01 = make_float4(pe_r * s,  pe_i * s,   pre_r * c,  pre_i * c);
        c23 = make_float4(pe_r * c,  pe_i * c,  -pre_r * s, -pre_i * s);
    }
    g_coef[2 * t]     = c01;
    g_coef[2 * t + 1] = c23;
}

// ============================================================
// Kernel 2: build R via identity basis. grid (64, 3), block 512.
// ============================================================
__global__ void build_R_kernel(const float* __restrict__ gamma) {
    __shared__ float x0r[TBR][NP], x0i[TBR][NP], x1r[TBR][NP], x1i[TBR][NP];
    const int iter = blockIdx.y;
    const int p = threadIdx.x & (NP - 1);
    const int r = threadIdx.x >> 7;            // 0..3
    const int gj = blockIdx.x * TBR + r;       // global basis index

    x0r[r][p] = (2 * p     == gj) ? 1.f : 0.f;  x0i[r][p] = 0.f;
    x1r[r][p] = (2 * p + 1 == gj) ? 1.f : 0.f;  x1i[r][p] = 0.f;
    __syncthreads();

    const float4* cbase = g_coef + (size_t)iter * NWG * NP * 2;
    for (int l = 0; l < NWG; l++) {
        float4 c01 = cbase[(l * NP + p) * 2];
        float4 c23 = cbase[(l * NP + p) * 2 + 1];
        float Ar = c01.x, Ai = c01.y, Br = c01.z, Bi = c01.w;
        float Cr = c23.x, Ci = c23.y, Dr = c23.z, Di = c23.w;
        if (!(l & 1)) {
            float ar = x0r[r][p], ai = x0i[r][p];
            float br = x1r[r][p], bi = x1i[r][p];
            x0r[r][p] = Ar*ar - Ai*ai + Br*br - Bi*bi;
            x0i[r][p] = Ar*ai + Ai*ar + Br*bi + Bi*br;
            x1r[r][p] = Cr*ar - Ci*ai + Dr*br - Di*bi;
            x1i[r][p] = Cr*ai + Ci*ar + Dr*bi + Di*br;
        } else if (p < NP - 1) {
            float ar = x1r[r][p],     ai = x1i[r][p];
            float br = x0r[r][p + 1], bi = x0i[r][p + 1];
            float y0r = Ar*ar - Ai*ai + Br*br - Bi*bi;
            float y0i = Ar*ai + Ai*ar + Br*bi + Bi*br;
            float y1r = Cr*ar - Ci*ai + Dr*br - Di*bi;
            float y1i = Cr*ai + Ci*ar + Dr*bi + Di*br;
            x1r[r][p] = y0r;     x1i[r][p] = y0i;
            x0r[r][p + 1] = y1r; x0i[r][p + 1] = y1i;
        }
        __syncthreads();
    }

    float s0, c0, s1, c1;
    sincosf(gamma[iter * NWG + 2 * p],     &s0, &c0);
    sincosf(gamma[iter * NWG + 2 * p + 1], &s1, &c1);
    size_t rowoff = ((size_t)iter * NWG + gj) * NWG;
    float xr = x0r[r][p], xi = x0i[r][p];
    g_Rre[rowoff + 2 * p] = xr * c0 - xi * s0;
    g_Rim[rowoff + 2 * p] = xr * s0 + xi * c0;
    xr = x1r[r][p]; xi = x1i[r][p];
    g_Rre[rowoff + 2 * p + 1] = xr * c1 - xi * s1;
    g_Rim[rowoff + 2 * p + 1] = xr * s1 + xi * c1;
}

// ============================================================
// Kernel 3: pack W^T into bf16 hi/lo planes.
// ============================================================
__global__ void pack_W_kernel() {
    int t = blockIdx.x * blockDim.x + threadIdx.x;
    if (t >= NITER * 512 * 512) return;
    int k = t & 511;
    int n = (t >> 9) & 511;
    int it = t >> 18;
    int a = k >> 1, c = n >> 1;
    int kb = k & 1, nb = n & 1;
    size_t ri = ((size_t)it * NWG + a) * NWG + c;
    float val;
    if (kb == nb)      val = g_Rre[ri];
    else if (kb == 1)  val = -g_Rim[ri];
    else               val = g_Rim[ri];
    __nv_bfloat16 h = __float2bfloat16_rn(val);
    gB_hi[t] = h;
    gB_lo[t] = __float2bfloat16_rn(val - __bfloat162float(h));
}

// ============================================================
// Kernel 4: prep A0 (vectorized: float4 in, uint4 out)
// ============================================================
__global__ void prep_A_kernel(const float* __restrict__ xr,
                              const float* __restrict__ xi) {
    int t = blockIdx.x * blockDim.x + threadIdx.x;
    if (t >= 8192 * 64) return;
    int cq = t & 63, m = t >> 6;
    float4 vr = *(const float4*)(xr + (size_t)m * 256 + cq * 4);
    float4 vi = *(const float4*)(xi + (size_t)m * 256 + cq * 4);
    float re[4] = { vr.x, vr.y, vr.z, vr.w };
    float im[4] = { vi.x, vi.y, vi.z, vi.w };
    __align__(16) __nv_bfloat16 hb[8], lb[8];
    #pragma unroll
    for (int q = 0; q < 4; q++) {
        __nv_bfloat16 h = __float2bfloat16_rn(re[q]);
        hb[2 * q] = h;  lb[2 * q] = __float2bfloat16_rn(re[q] - __bfloat162float(h));
        h = __float2bfloat16_rn(im[q]);
        hb[2 * q + 1] = h;  lb[2 * q + 1] = __float2bfloat16_rn(im[q] - __bfloat162float(h));
    }
    size_t o = (size_t)m * 512 + cq * 8;
    *(uint4*)(gA_hi[0] + o) = *(const uint4*)hb;
    *(uint4*)(gA_lo[0] + o) = *(const uint4*)lb;
}

// ============================================================
// Kernel 5: bf16 split-2 GEMM (mma.sync) + fused epilogue.
// grid (64, 4), 256 threads = 8 warps; warp tile 64x32; 2 CTAs/SM.
// Single __syncthreads per K-chunk:
//   wait(ch) -> sync -> issue(ch+2)  [overwrites stage ch-1: all threads
//   finished reading it before this sync] -> consume(ch).
// ============================================================
__global__ void __launch_bounds__(256, 2) gemm_kernel(int iter) {
    extern __shared__ char smraw[];
    const uint32_t smem_u = (uint32_t)__cvta_generic_to_shared(smraw);

    const int tid = threadIdx.x;
    const int lane = tid & 31, wid = tid >> 5;
    const int wm = wid & 1, wn = wid >> 1;
    const int m0 = blockIdx.x * BM;
    const int n0 = blockIdx.y * BN;
    const int rd = iter & 1;

    const __nv_bfloat16* __restrict__ Ah = gA_hi[rd];
    const __nv_bfloat16* __restrict__ Al = gA_lo[rd];
    const __nv_bfloat16* __restrict__ Bh = gB_hi + (size_t)iter * 512 * 512;
    const __nv_bfloat16* __restrict__ Bl = gB_lo + (size_t)iter * 512 * 512;
    const __nv_bfloat16* planes[4] = { Ah, Al, Bh, Bl };

    // loader: one K-chunk (BK=32) into stage buf. 2048 cp16 = 8/thread.
    auto issue_loads = [&](int ch, int buf) {
        const int k0 = ch * BK;
        uint32_t sbase = smem_u + buf * STG_BYTES;
        #pragma unroll
        for (int pl = 0; pl < 4; pl++) {
            const __nv_bfloat16* src = planes[pl];
            int rowbase = (pl < 2) ? m0 : n0;
            #pragma unroll
            for (int qq = 0; qq < 2; qq++) {
                int q = qq * 256 + tid;
                int row = q >> 2, c = q & 3;
                const void* g = src + (size_t)(rowbase + row) * 512 + k0 + c * 8;
                cp16(sbase + pl * STG_PL + swz(row, c), g);
            }
        }
    };

    int rowA[4], rowB[2];
    #pragma unroll
    for (int ms = 0; ms < 4; ms++)
        rowA[ms] = wm * 64 + ms * 16 + ((lane >> 3) & 1) * 8 + (lane & 7);
    #pragma unroll
    for (int nb = 0; nb < 2; nb++)
        rowB[nb] = wn * 32 + nb * 16 + ((lane >> 3) & 1) * 8 + (lane & 7);
    const int khalf = lane >> 4;   // 0/1

    float acc[4][4][4];
    #pragma unroll
    for (int i = 0; i < 4; i++)
        #pragma unroll
        for (int j = 0; j < 4; j++)
            #pragma unroll
            for (int q = 0; q < 4; q++) acc[i][j][q] = 0.f;

    issue_loads(0, 0); CP_COMMIT();
    issue_loads(1, 1); CP_COMMIT();

    for (int ch = 0; ch < NKCH; ch++) {
        const int b = ch % NSTG;
        // ensure stage ch data landed
        if (ch + 1 < NKCH) { CP_WAIT1(); } else { CP_WAIT0(); }
        __syncthreads();
        // producer runs ahead: fill stage ch+2 (buffer held stage ch-1,
        // fully consumed by every thread before the sync above)
        if (ch + 2 < NKCH) { issue_loads(ch + 2, (ch + 2) % NSTG); CP_COMMIT(); }

        const uint32_t stbase = smem_u + b * STG_BYTES;
        #pragma unroll
        for (int kk = 0; kk < 2; kk++) {
            const int kidx = kk * 2 + khalf;
            uint32_t bh[2][4], bl[2][4];
            #pragma unroll
            for (int nb = 0; nb < 2; nb++) {
                uint32_t bd = stbase + 2 * STG_PL + swz(rowB[nb], kidx);
                LDSM4(bh[nb], bd);
                LDSM4(bl[nb], bd + STG_PL);
            }
            #pragma unroll
            for (int ms = 0; ms < 4; ms++) {
                uint32_t ah[4], al[4];
                uint32_t ad = stbase + swz(rowA[ms], kidx);
                LDSM4(ah, ad);
                LDSM4(al, ad + STG_PL);
                #pragma unroll
                for (int ns = 0; ns < 4; ns++) {
                    int nb = ns >> 1, od = ns & 1;
                    mma_bf16(acc[ms][ns], ah, bh[nb][od], bh[nb][2 + od]);
                    mma_bf16(acc[ms][ns], ah, bl[nb][od], bl[nb][2 + od]);
                    mma_bf16(acc[ms][ns], al, bh[nb][od], bh[nb][2 + od]);
                }
            }
        }
        // no trailing sync: top-of-loop sync of iteration ch+1 provides it
    }

    // fused epilogue (fragment (re,im) pairs are thread-local)
    const int nxt = (iter + 1) & 1;
    const int rowbase = m0 + wm * 64 + (lane >> 2);
    const int colbase = n0 + wn * 32 + (lane & 3) * 2;

    #pragma unroll
    for (int ms = 0; ms < 4; ms++) {
        #pragma unroll
        for (int ns = 0; ns < 4; ns++) {
            #pragma unroll
            for (int h = 0; h < 2; h++) {
                int row = rowbase + ms * 16 + h * 8;
                int col = colbase + ns * 8;
                float re = acc[ms][ns][2 * h];
                float im = acc[ms][ns][2 * h + 1];
                if (iter != NITER - 1) {
                    float phase = HALF_G * (re * re + im * im) + HALF_PHIB;
                    float sp, cp; __sincosf(phase, &sp, &cp);
                    float sc = SQ09 * cp;
                    float yre = sc * (cp * re + sp * im);
                    float yim = sc * (cp * im - sp * re);
                    __nv_bfloat16 hr = __float2bfloat16_rn(yre);
                    __nv_bfloat16 hi = __float2bfloat16_rn(yim);
                    __nv_bfloat16 lr = __float2bfloat16_rn(yre - __bfloat162float(hr));
                    __nv_bfloat16 li = __float2bfloat16_rn(yim - __bfloat162float(hi));
                    size_t o = (size_t)row * 512 + col;
                    *(__nv_bfloat162*)(gA_hi[nxt] + o) = __nv_bfloat162(hr, hi);
                    *(__nv_bfloat162*)(gA_lo[nxt] + o) = __nv_bfloat162(lr, li);
                } else {
                    gV[(size_t)row * 256 + (col >> 1)] = re * re + im * im;
                }
            }
        }
    }
}

// ============================================================
// Kernel 6: row-wise L2 normalize of intensity, write 10 cols
// ============================================================
__global__ void normalize_kernel(float* __restrict__ out) {
    int w = (blockIdx.x * blockDim.x + threadIdx.x) >> 5;
    int lane = threadIdx.x & 31;
    if (w >= 8192) return;
    const float* v = gV + (size_t)w * 256;
    float first = 0.f, sum = 0.f;
    #pragma unroll
    for (int j = 0; j < 8; j++) {
        float x = v[lane + 32 * j];
        if (j == 0) first = x;
        sum += x * x;
    }
    #pragma unroll
    for (int o = 16; o; o >>= 1) sum += __shfl_xor_sync(0xFFFFFFFFu, sum, o);
    float inv = 1.f / fmaxf(sqrtf(sum), 1e-12f);
    if (lane < 10) out[w * 10 + lane] = first * inv;
}

// ============================================================
extern "C" void kernel_launch(void* const* d_in, const int* in_sizes, int n_in,
                              void* d_out, int out_size) {
    const float* xre   = (const float*)d_in[0];
    const float* xim   = (const float*)d_in[1];
    const float* theta = (const float*)d_in[2];
    const float* phi   = (const float*)d_in[3];
    const float* gamma = (const float*)d_in[4];
    float* out = (float*)d_out;

    static int attr_set = 0;
    if (!attr_set) {
        cudaFuncSetAttribute(gemm_kernel,
                             cudaFuncAttributeMaxDynamicSharedMemorySize, SMEM_DYN);
        attr_set = 1;
    }

    coef_kernel<<<(NITER * NWG * NP + 255) / 256, 256>>>(theta, phi);
    build_R_kernel<<<dim3(NWG / TBR, NITER), 512>>>(gamma);
    pack_W_kernel<<<(NITER * 512 * 512) / 256, 256>>>();
    prep_A_kernel<<<(8192 * 64) / 256, 256>>>(xre, xim);
    for (int it = 0; it < NITER; it++)
        gemm_kernel<<<dim3(8192 / BM, 512 / BN), 256, SMEM_DYN>>>(it);
    normalize_kernel<<<8192 / 8, 256>>>(out);
}

// round 7
// speedup vs baseline: 2.5179x; 1.0376x over previous
#include <cuda_runtime.h>
#include <cuda_bf16.h>
#include <math.h>
#include <stdint.h>

#define NWG   256
#define NP    128
#define NITER 3
#define TBR   4

#define HALF_G    0.07853981633974483f   // 0.5 * 0.05 * pi
#define HALF_PHIB 1.5707963267948966f    // 0.5 * pi
#define SQ09      0.9486832980505138f    // sqrt(1 - 0.1)

// GEMM tiling
#define BM 128
#define BN 128
#define BK 32
#define NKCH 16                          // 512 / 32
#define STG_PL   8192                    // bytes per plane per stage (128 rows * 64B)
#define STG_BYTES (4 * STG_PL)           // Ah, Al, Bh, Bl = 32KB per stage
#define NSTG 3
#define SMEM_DYN (NSTG * STG_BYTES)      // 96KB

// Tiled global layouts (pre-swizzled 8KB blocks = 4096 bf16):
//   A: [mtile 64][chunk 16][plane 2][4096]   B: [ntile 4][chunk 16][plane 2][4096]
#define A_ELEMS (64 * 16 * 2 * 4096)     // 8.39M elems = 16 MB
#define B_ELEMS (4 * 16 * 2 * 4096)      // 524288 elems = 1 MB

// ---------------- device scratch (no allocs allowed) ----------------
__device__ float4 g_coef[NITER * NWG * NP * 2];
__device__ float  g_Rre[NITER * NWG * NWG];
__device__ float  g_Rim[NITER * NWG * NWG];
__device__ __nv_bfloat16 gBt[NITER * B_ELEMS];
__device__ __nv_bfloat16 gAt[2][A_ELEMS];
__device__ float gV[8192 * 256];

// ---------------- PTX helpers ----------------
__device__ __forceinline__ uint32_t smem_u32(const void* p) {
    return (uint32_t)__cvta_generic_to_shared(p);
}

#define LDSM4(r, addr)                                                         \
    asm volatile("ldmatrix.sync.aligned.m8n8.x4.shared.b16 {%0,%1,%2,%3}, [%4];" \
        : "=r"((r)[0]), "=r"((r)[1]), "=r"((r)[2]), "=r"((r)[3]) : "r"(addr))

__device__ __forceinline__ void mma_bf16(float* d, const uint32_t* a,
                                         uint32_t b0, uint32_t b1) {
    asm volatile(
        "mma.sync.aligned.m16n8k16.row.col.f32.bf16.bf16.f32 "
        "{%0,%1,%2,%3}, {%4,%5,%6,%7}, {%8,%9}, {%0,%1,%2,%3};"
        : "+f"(d[0]), "+f"(d[1]), "+f"(d[2]), "+f"(d[3])
        : "r"(a[0]), "r"(a[1]), "r"(a[2]), "r"(a[3]), "r"(b0), "r"(b1));
}

// 1D bulk async copy global -> shared, mbarrier tx-completion (sm_90 generic)
__device__ __forceinline__ void bulk_g2s(uint32_t dst, const void* src,
                                         uint32_t bytes, uint32_t mb) {
    asm volatile(
        "cp.async.bulk.shared::cluster.global.mbarrier::complete_tx::bytes "
        "[%0], [%1], %2, [%3];"
        :: "r"(dst), "l"(src), "r"(bytes), "r"(mb) : "memory");
}
#define MBAR_INIT(mb, n) asm volatile("mbarrier.init.shared.b64 [%0], %1;" :: "r"(mb), "r"((uint32_t)(n)) : "memory")
#define MBAR_EXPECT_TX(mb, tx) asm volatile("mbarrier.arrive.expect_tx.shared.b64 _, [%0], %1;" :: "r"(mb), "r"((uint32_t)(tx)) : "memory")
#define FENCE_ASYNC() asm volatile("fence.proxy.async.shared::cta;" ::: "memory")

#define MBAR_WAIT(mb, par) do {                                                    \
    uint32_t _mb = (mb); uint32_t _p = (par); uint32_t _done;                      \
    asm volatile("{\n\t.reg .pred p;\n\t"                                          \
        "mbarrier.try_wait.parity.acquire.cta.shared::cta.b64 p, [%1], %2;\n\t"    \
        "selp.b32 %0, 1, 0, p;\n\t}"                                               \
        : "=r"(_done) : "r"(_mb), "r"(_p) : "memory");                             \
    if (!_done) {                                                                  \
        asm volatile("{\n\t.reg .pred P1;\n\t"                                     \
        "WL_%=:\n\t"                                                               \
        "mbarrier.try_wait.parity.acquire.cta.shared::cta.b64 P1, [%0], %1, 0x989680;\n\t" \
        "@P1 bra.uni WD_%=;\n\t"                                                   \
        "bra.uni WL_%=;\n\t"                                                       \
        "WD_%=:\n\t}" :: "r"(_mb), "r"(_p) : "memory");                            \
    } } while (0)

// swizzled byte offset within an 8KB plane block (row 0..127, 16B chunk c 0..3)
__device__ __forceinline__ uint32_t swz(int row, int c) {
    return (uint32_t)(row * 64 + ((c ^ ((row >> 1) & 3)) << 4));
}

// ============================================================
// Kernel 1: fold theta/phi into 2x2 complex MZI matrices
// ============================================================
__global__ void coef_kernel(const float* __restrict__ theta,
                            const float* __restrict__ phi) {
    int t = blockIdx.x * blockDim.x + threadIdx.x;
    const int total = NITER * NWG * NP;
    if (t >= total) return;
    int pair  = t % NP;
    int layer = (t / NP) % NWG;

    float4 c01, c23;
    if ((layer & 1) && pair == NP - 1) {
        c01 = make_float4(1.f, 0.f, 0.f, 0.f);
        c23 = make_float4(0.f, 0.f, 1.f, 0.f);
    } else {
        float h = 0.5f * theta[t];
        float s, c;  sincosf(h, &s, &c);
        float sp, cp; sincosf(phi[t], &sp, &cp);
        float pre_r = -s, pre_i = c;
        float pe_r = pre_r * cp - pre_i * sp;
        float pe_i = pre_r * sp + pre_i * cp;
        c01 = make_float4(pe_r * s,  pe_i * s,   pre_r * c,  pre_i * c);
        c23 = make_float4(pe_r * c,  pe_i * c,  -pre_r * s, -pre_i * s);
    }
    g_coef[2 * t]     = c01;
    g_coef[2 * t + 1] = c23;
}

// ============================================================
// Kernel 2: build R via identity basis. grid (64, 3), block 512.
// ============================================================
__global__ void build_R_kernel(const float* __restrict__ gamma) {
    __shared__ float x0r[TBR][NP], x0i[TBR][NP], x1r[TBR][NP], x1i[TBR][NP];
    const int iter = blockIdx.y;
    const int p = threadIdx.x & (NP - 1);
    const int r = threadIdx.x >> 7;            // 0..3
    const int gj = blockIdx.x * TBR + r;       // global basis index

    x0r[r][p] = (2 * p     == gj) ? 1.f : 0.f;  x0i[r][p] = 0.f;
    x1r[r][p] = (2 * p + 1 == gj) ? 1.f : 0.f;  x1i[r][p] = 0.f;
    __syncthreads();

    const float4* cbase = g_coef + (size_t)iter * NWG * NP * 2;
    for (int l = 0; l < NWG; l++) {
        float4 c01 = cbase[(l * NP + p) * 2];
        float4 c23 = cbase[(l * NP + p) * 2 + 1];
        float Ar = c01.x, Ai = c01.y, Br = c01.z, Bi = c01.w;
        float Cr = c23.x, Ci = c23.y, Dr = c23.z, Di = c23.w;
        if (!(l & 1)) {
            float ar = x0r[r][p], ai = x0i[r][p];
            float br = x1r[r][p], bi = x1i[r][p];
            x0r[r][p] = Ar*ar - Ai*ai + Br*br - Bi*bi;
            x0i[r][p] = Ar*ai + Ai*ar + Br*bi + Bi*br;
            x1r[r][p] = Cr*ar - Ci*ai + Dr*br - Di*bi;
            x1i[r][p] = Cr*ai + Ci*ar + Dr*bi + Di*br;
        } else if (p < NP - 1) {
            float ar = x1r[r][p],     ai = x1i[r][p];
            float br = x0r[r][p + 1], bi = x0i[r][p + 1];
            float y0r = Ar*ar - Ai*ai + Br*br - Bi*bi;
            float y0i = Ar*ai + Ai*ar + Br*bi + Bi*br;
            float y1r = Cr*ar - Ci*ai + Dr*br - Di*bi;
            float y1i = Cr*ai + Ci*ar + Dr*bi + Di*br;
            x1r[r][p] = y0r;     x1i[r][p] = y0i;
            x0r[r][p + 1] = y1r; x0i[r][p + 1] = y1i;
        }
        __syncthreads();
    }

    float s0, c0, s1, c1;
    sincosf(gamma[iter * NWG + 2 * p],     &s0, &c0);
    sincosf(gamma[iter * NWG + 2 * p + 1], &s1, &c1);
    size_t rowoff = ((size_t)iter * NWG + gj) * NWG;
    float xr = x0r[r][p], xi = x0i[r][p];
    g_Rre[rowoff + 2 * p] = xr * c0 - xi * s0;
    g_Rim[rowoff + 2 * p] = xr * s0 + xi * c0;
    xr = x1r[r][p]; xi = x1i[r][p];
    g_Rre[rowoff + 2 * p + 1] = xr * c1 - xi * s1;
    g_Rim[rowoff + 2 * p + 1] = xr * s1 + xi * c1;
}

// ============================================================
// Kernel 3: pack W^T into tiled, pre-swizzled bf16 hi/lo blocks.
// W[2a][2c]=Rr, W[2a+1][2c]=-Ri, W[2a][2c+1]=Ri, W[2a+1][2c+1]=Rr
// thread handles one (it, n, kq): 8 consecutive k of row n.
// ============================================================
__global__ void pack_W_kernel() {
    int t = blockIdx.x * blockDim.x + threadIdx.x;
    if (t >= NITER * 512 * 64) return;
    int kq = t & 63;
    int n  = (t >> 6) & 511;
    int it = t >> 15;
    int c = n >> 1, nb = n & 1;

    __align__(16) __nv_bfloat16 hb[8], lb[8];
    #pragma unroll
    for (int q = 0; q < 8; q++) {
        int k = kq * 8 + q;
        int a = k >> 1, kb = k & 1;
        size_t ri = ((size_t)it * NWG + a) * NWG + c;
        float val;
        if (kb == nb)      val = g_Rre[ri];
        else if (kb == 1)  val = -g_Rim[ri];
        else               val = g_Rim[ri];
        __nv_bfloat16 h = __float2bfloat16_rn(val);
        hb[q] = h;
        lb[q] = __float2bfloat16_rn(val - __bfloat162float(h));
    }
    int ntile = n >> 7, r = n & 127;
    int chunk = kq >> 2, cw = kq & 3;
    size_t blk = (size_t)it * B_ELEMS + (size_t)((ntile * 16 + chunk) * 2) * 4096;
    size_t off = (size_t)r * 32 + ((cw ^ ((r >> 1) & 3)) << 3);
    *(uint4*)(gBt + blk + off)        = *(const uint4*)hb;
    *(uint4*)(gBt + blk + 4096 + off) = *(const uint4*)lb;
}

// ============================================================
// Kernel 4: prep A0 into tiled, pre-swizzled layout.
// thread: (m, cq) -> realified cols 8cq..8cq+7 (4 complex cols)
// ============================================================
__global__ void prep_A_kernel(const float* __restrict__ xr,
                              const float* __restrict__ xi) {
    int t = blockIdx.x * blockDim.x + threadIdx.x;
    if (t >= 8192 * 64) return;
    int cq = t & 63, m = t >> 6;
    float4 vr = *(const float4*)(xr + (size_t)m * 256 + cq * 4);
    float4 vi = *(const float4*)(xi + (size_t)m * 256 + cq * 4);
    float re[4] = { vr.x, vr.y, vr.z, vr.w };
    float im[4] = { vi.x, vi.y, vi.z, vi.w };
    __align__(16) __nv_bfloat16 hb[8], lb[8];
    #pragma unroll
    for (int q = 0; q < 4; q++) {
        __nv_bfloat16 h = __float2bfloat16_rn(re[q]);
        hb[2 * q] = h;  lb[2 * q] = __float2bfloat16_rn(re[q] - __bfloat162float(h));
        h = __float2bfloat16_rn(im[q]);
        hb[2 * q + 1] = h;  lb[2 * q + 1] = __float2bfloat16_rn(im[q] - __bfloat162float(h));
    }
    int mtile = m >> 7, r = m & 127;
    int chunk = cq >> 2, cw = cq & 3;
    size_t blk = (size_t)((mtile * 16 + chunk) * 2) * 4096;
    size_t off = (size_t)r * 32 + ((cw ^ ((r >> 1) & 3)) << 3);
    *(uint4*)(gAt[0] + blk + off)        = *(const uint4*)hb;
    *(uint4*)(gAt[0] + blk + 4096 + off) = *(const uint4*)lb;
}

// ============================================================
// Kernel 5: bf16 split-2 GEMM, cp.async.bulk producer + mbarrier.
// grid (64, 4), 256 threads, 2 CTAs/SM. 2 bulk ops / chunk / CTA.
// ============================================================
__global__ void __launch_bounds__(256, 2) gemm_kernel(int iter) {
    extern __shared__ char smraw[];
    __shared__ __align__(8) unsigned long long s_mbar[NSTG];
    const uint32_t smem_u = (uint32_t)__cvta_generic_to_shared(smraw);

    const int tid = threadIdx.x;
    const int lane = tid & 31, wid = tid >> 5;
    const int wm = wid & 1, wn = wid >> 1;
    const int m0 = blockIdx.x * BM;
    const int n0 = blockIdx.y * BN;
    const int rd = iter & 1;

    const __nv_bfloat16* __restrict__ At =
        gAt[rd] + (size_t)((m0 >> 7) * 16) * 2 * 4096;
    const __nv_bfloat16* __restrict__ Bt =
        gBt + (size_t)iter * B_ELEMS + (size_t)((n0 >> 7) * 16) * 2 * 4096;

    uint32_t mb[NSTG];
    #pragma unroll
    for (int s = 0; s < NSTG; s++) mb[s] = smem_u32(&s_mbar[s]);
    if (tid == 0) {
        #pragma unroll
        for (int s = 0; s < NSTG; s++) MBAR_INIT(mb[s], 1);
    }
    __syncthreads();

    auto issue = [&](int ch) {
        int s = ch % NSTG;
        uint32_t dst = smem_u + s * STG_BYTES;
        MBAR_EXPECT_TX(mb[s], 2 * 16384);
        bulk_g2s(dst,         At + (size_t)ch * 8192, 16384, mb[s]);   // Ah|Al
        bulk_g2s(dst + 16384, Bt + (size_t)ch * 8192, 16384, mb[s]);   // Bh|Bl
    };

    if (tid == 0) { issue(0); issue(1); }

    int rowA[4], rowB[2];
    #pragma unroll
    for (int ms = 0; ms < 4; ms++)
        rowA[ms] = wm * 64 + ms * 16 + ((lane >> 3) & 1) * 8 + (lane & 7);
    #pragma unroll
    for (int nb = 0; nb < 2; nb++)
        rowB[nb] = wn * 32 + nb * 16 + ((lane >> 3) & 1) * 8 + (lane & 7);
    const int khalf = lane >> 4;   // 0/1

    float acc[4][4][4];
    #pragma unroll
    for (int i = 0; i < 4; i++)
        #pragma unroll
        for (int j = 0; j < 4; j++)
            #pragma unroll
            for (int q = 0; q < 4; q++) acc[i][j][q] = 0.f;

    for (int ch = 0; ch < NKCH; ch++) {
        const int b = ch % NSTG;
        MBAR_WAIT(mb[b], (ch / NSTG) & 1);
        __syncthreads();   // all threads finished consuming stage ch-1 -> refillable
        if (tid == 0 && ch + 2 < NKCH) { FENCE_ASYNC(); issue(ch + 2); }

        const uint32_t stbase = smem_u + b * STG_BYTES;
        #pragma unroll
        for (int kk = 0; kk < 2; kk++) {
            const int kidx = kk * 2 + khalf;
            uint32_t bh[2][4], bl[2][4];
            #pragma unroll
            for (int nb = 0; nb < 2; nb++) {
                uint32_t bd = stbase + 2 * STG_PL + swz(rowB[nb], kidx);
                LDSM4(bh[nb], bd);
                LDSM4(bl[nb], bd + STG_PL);
            }
            #pragma unroll
            for (int ms = 0; ms < 4; ms++) {
                uint32_t ah[4], al[4];
                uint32_t ad = stbase + swz(rowA[ms], kidx);
                LDSM4(ah, ad);
                LDSM4(al, ad + STG_PL);
                #pragma unroll
                for (int ns = 0; ns < 4; ns++) {
                    int nb = ns >> 1, od = ns & 1;
                    mma_bf16(acc[ms][ns], ah, bh[nb][od], bh[nb][2 + od]);
                    mma_bf16(acc[ms][ns], ah, bl[nb][od], bl[nb][2 + od]);
                    mma_bf16(acc[ms][ns], al, bh[nb][od], bh[nb][2 + od]);
                }
            }
        }
    }

    // fused epilogue -> tiled swizzled gA[nxt] (or gV on last iter)
    const int nxt = (iter + 1) & 1;
    const int rowbase = m0 + wm * 64 + (lane >> 2);
    const int colbase = n0 + wn * 32 + (lane & 3) * 2;

    #pragma unroll
    for (int ms = 0; ms < 4; ms++) {
        #pragma unroll
        for (int ns = 0; ns < 4; ns++) {
            #pragma unroll
            for (int h = 0; h < 2; h++) {
                int row = rowbase + ms * 16 + h * 8;
                int col = colbase + ns * 8;
                float re = acc[ms][ns][2 * h];
                float im = acc[ms][ns][2 * h + 1];
                if (iter != NITER - 1) {
                    float phase = HALF_G * (re * re + im * im) + HALF_PHIB;
                    float sp, cp; __sincosf(phase, &sp, &cp);
                    float sc = SQ09 * cp;
                    float yre = sc * (cp * re + sp * im);
                    float yim = sc * (cp * im - sp * re);
                    __nv_bfloat16 hr = __float2bfloat16_rn(yre);
                    __nv_bfloat16 hi = __float2bfloat16_rn(yim);
                    __nv_bfloat16 lr = __float2bfloat16_rn(yre - __bfloat162float(hr));
                    __nv_bfloat16 li = __float2bfloat16_rn(yim - __bfloat162float(hi));
                    int mtile = row >> 7, r = row & 127;
                    int chunk = col >> 5, cw = (col >> 3) & 3;
                    size_t blk = (size_t)((mtile * 16 + chunk) * 2) * 4096;
                    size_t off = (size_t)r * 32 + ((cw ^ ((r >> 1) & 3)) << 3)
                               + (col & 7);
                    *(__nv_bfloat162*)(gAt[nxt] + blk + off) = __nv_bfloat162(hr, hi);
                    *(__nv_bfloat162*)(gAt[nxt] + blk + 4096 + off) = __nv_bfloat162(lr, li);
                } else {
                    gV[(size_t)row * 256 + (col >> 1)] = re * re + im * im;
                }
            }
        }
    }
}

// ============================================================
// Kernel 6: row-wise L2 normalize of intensity, write 10 cols
// ============================================================
__global__ void normalize_kernel(float* __restrict__ out) {
    int w = (blockIdx.x * blockDim.x + threadIdx.x) >> 5;
    int lane = threadIdx.x & 31;
    if (w >= 8192) return;
    const float* v = gV + (size_t)w * 256;
    float first = 0.f, sum = 0.f;
    #pragma unroll
    for (int j = 0; j < 8; j++) {
        float x = v[lane + 32 * j];
        if (j == 0) first = x;
        sum += x * x;
    }
    #pragma unroll
    for (int o = 16; o; o >>= 1) sum += __shfl_xor_sync(0xFFFFFFFFu, sum, o);
    float inv = 1.f / fmaxf(sqrtf(sum), 1e-12f);
    if (lane < 10) out[w * 10 + lane] = first * inv;
}

// ============================================================
extern "C" void kernel_launch(void* const* d_in, const int* in_sizes, int n_in,
                              void* d_out, int out_size) {
    const float* xre   = (const float*)d_in[0];
    const float* xim   = (const float*)d_in[1];
    const float* theta = (const float*)d_in[2];
    const float* phi   = (const float*)d_in[3];
    const float* gamma = (const float*)d_in[4];
    float* out = (float*)d_out;

    static int attr_set = 0;
    if (!attr_set) {
        cudaFuncSetAttribute(gemm_kernel,
                             cudaFuncAttributeMaxDynamicSharedMemorySize, SMEM_DYN);
        attr_set = 1;
    }

    coef_kernel<<<(NITER * NWG * NP + 255) / 256, 256>>>(theta, phi);
    build_R_kernel<<<dim3(NWG / TBR, NITER), 512>>>(gamma);
    pack_W_kernel<<<(NITER * 512 * 64) / 256, 256>>>();
    prep_A_kernel<<<(8192 * 64) / 256, 256>>>(xre, xim);
    for (int it = 0; it < NITER; it++)
        gemm_kernel<<<dim3(8192 / BM, 512 / BN), 256, SMEM_DYN>>>(it);
    normalize_kernel<<<8192 / 8, 256>>>(out);
}